// round 3
// baseline (speedup 1.0000x reference)
#include <cuda_runtime.h>
#include <math.h>

#define Bx 256
#define Sx 256
#define Ex 300
#define Hx 300
#define G4 1200     // 4*H
#define Cc 600      // 2*H channels
#define SP 258      // S + 2 (padded rows for conv)
#define Mx 65536    // B*S
#define KCONV 1800  // 3*Cc

// ---------------- scratch (__device__ globals; zero-init at load) -------------
__device__ float d_text[(size_t)Mx * Ex];       // embeddings [B*S, E]
__device__ float d_xg_f[(size_t)Mx * G4];       // input-gate precompute fwd (gate-interleaved cols)
__device__ float d_xg_b[(size_t)Mx * G4];       // same for bwd weights (on UNreversed text)
__device__ float d_to[(size_t)Mx * Cc];         // text_out [B,S,2H] (masked)
__device__ float d_xin1[(size_t)Bx * SP * Cc];  // conv1 input, padded rows (pads stay 0)
__device__ float d_xin2[(size_t)Bx * SP * Cc];  // conv2 input, padded rows
__device__ float d_y2[(size_t)Mx * Cc];         // relu(conv2)
__device__ float d_h[2 * 512 * Hx];             // h ping-pong, rows: 0..255 fwd, 256..511 bwd
__device__ float d_c[512 * Hx];                 // cell state
__device__ float d_Wihf_t[Ex * G4];             // [k][j*4+g]
__device__ float d_Wihb_t[Ex * G4];
__device__ float d_Whhf_t[Hx * G4];
__device__ float d_Whhb_t[Hx * G4];
__device__ float d_bif[G4];
__device__ float d_bib[G4];
__device__ float d_cw1[KCONV * Cc];             // [(k*600+i)][o]
__device__ float d_cw2[KCONV * Cc];
__device__ float d_pw[Mx];
__device__ int   d_L[Bx], d_asp[Bx], d_left[Bx];
__device__ float d_v[Bx * Cc];
__device__ float d_logits[Mx];

// ---------------- meta: lengths + position weights ---------------------------
__global__ void k_meta(const int* __restrict__ cat, const int* __restrict__ aspi,
                       const int* __restrict__ lefti) {
    __shared__ int s[3];
    int b = blockIdx.x, t = threadIdx.x;
    if (t < 3) s[t] = 0;
    __syncthreads();
    if (cat[b * Sx + t] != 0) atomicAdd(&s[0], 1);
    if (t < 16 && aspi[b * 16 + t] != 0) atomicAdd(&s[1], 1);
    if (t < 128 && lefti[b * 128 + t] != 0) atomicAdd(&s[2], 1);
    __syncthreads();
    int L = s[0], A = s[1], Le = s[2];
    if (t == 0) { d_L[b] = L; d_asp[b] = A; d_left[b] = Le; }
    float na = (float)(L - A);
    int right = Le + A - 1;
    float w;
    if (t < Le)           w = 1.0f - (float)(Le - t) / na;
    else if (t <= right)  w = 0.0f;
    else if (t < L)       w = 1.0f - (float)(t - right) / na;
    else                  w = 0.0f;
    d_pw[b * Sx + t] = w;
}

// ---------------- zero LSTM state each invocation -----------------------------
__global__ void k_zero() {
    int stride = gridDim.x * blockDim.x;
    for (int i = blockIdx.x * blockDim.x + threadIdx.x; i < 2 * 512 * Hx; i += stride)
        d_h[i] = 0.f;
    for (int i = blockIdx.x * blockDim.x + threadIdx.x; i < 512 * Hx; i += stride)
        d_c[i] = 0.f;
}

// ---------------- weight reshapes ---------------------------------------------
__global__ void k_prep(const float* __restrict__ Wihf, const float* __restrict__ Whhf,
                       const float* __restrict__ bf,
                       const float* __restrict__ Wihb, const float* __restrict__ Whhb,
                       const float* __restrict__ bbv,
                       const float* __restrict__ c1w, const float* __restrict__ c2w) {
    int stride = gridDim.x * blockDim.x;
    int tid0 = blockIdx.x * blockDim.x + threadIdx.x;
    // W_ih / W_hh -> [k][j*4+g]
    for (int idx = tid0; idx < Ex * G4; idx += stride) {
        int k = idx / G4, col = idx - k * G4;
        int j = col >> 2, g = col & 3;
        int src = (g * Hx + j) * Ex + k;   // Ex == Hx == 300
        d_Wihf_t[idx] = Wihf[src];
        d_Wihb_t[idx] = Wihb[src];
        d_Whhf_t[idx] = Whhf[src];
        d_Whhb_t[idx] = Whhb[src];
    }
    for (int idx = tid0; idx < G4; idx += stride) {
        int j = idx >> 2, g = idx & 3;
        d_bif[idx] = bf[g * Hx + j];
        d_bib[idx] = bbv[g * Hx + j];
    }
    // conv weights [O,I,3] -> [(k*600+i)][o]
    for (int idx = tid0; idx < KCONV * Cc; idx += stride) {
        int o = idx % Cc, r = idx / Cc;
        int kk = r / Cc, i = r - kk * Cc;
        size_t src = (size_t)o * KCONV + i * 3 + kk;
        d_cw1[idx] = c1w[src];
        d_cw2[idx] = c2w[src];
    }
}

// ---------------- embedding gather --------------------------------------------
__global__ void k_embed(const int* __restrict__ cat, const float* __restrict__ emb) {
    int stride = gridDim.x * blockDim.x;
    for (int idx = blockIdx.x * blockDim.x + threadIdx.x; idx < Mx * Ex; idx += stride) {
        int m = idx / Ex, e = idx - m * Ex;
        d_text[idx] = emb[(size_t)cat[m] * Ex + e];
    }
}

// ---------------- generic SGEMM 128x128x8, 8x8 per thread ----------------------
// CFG 0: xg_f  (A=text,  B=Wihf_t, bias=d_bif, N=1200, K=300)
// CFG 1: xg_b  (A=text,  B=Wihb_t, bias=d_bib, N=1200, K=300)
// CFG 2: conv1 (A=xin1 padded windows, B=cw1, bias=ext, relu, *pw, out padded xin2)
// CFG 3: conv2 (A=xin2 padded windows, B=cw2, bias=ext, relu, out y2)
template <int CFG>
__global__ __launch_bounds__(256, 2)
void sgemm(const float* __restrict__ extbias) {
    constexpr int  N      = (CFG < 2) ? G4 : Cc;
    constexpr int  K      = (CFG < 2) ? Ex : KCONV;
    constexpr bool CONVA  = (CFG >= 2);
    constexpr bool RELU   = (CFG >= 2);
    constexpr bool PWM    = (CFG == 2);
    constexpr bool PADOUT = (CFG == 2);

    const float* A    = (CFG < 2) ? d_text : (CFG == 2 ? d_xin1 : d_xin2);
    const float* Bw   = (CFG == 0) ? d_Wihf_t : (CFG == 1) ? d_Wihb_t
                        : (CFG == 2) ? d_cw1 : d_cw2;
    const float* bias = (CFG == 0) ? d_bif : (CFG == 1) ? d_bib : extbias;
    float*       Cout = (CFG == 0) ? d_xg_f : (CFG == 1) ? d_xg_b
                        : (CFG == 2) ? d_xin2 : d_y2;

    __shared__ float As[8][128];
    __shared__ float Bs[8][128];

    int tid = threadIdx.x;
    int m0 = blockIdx.y * 128;
    int n0 = blockIdx.x * 128;

    int arow = tid >> 1;            // 0..127
    int akq  = (tid & 1) * 4;       // 0 or 4
    int brow = tid >> 5;            // 0..7
    int bc   = (tid & 31) * 4;      // 0..124

    int m_a = m0 + arow;
    size_t abase;
    if (CONVA) {
        int bb = m_a >> 8, ss = m_a & 255;
        abase = ((size_t)(bb * SP + ss)) * Cc;    // window starts at padded row s
    } else {
        abase = (size_t)m_a * K;
    }

    float acc[8][8];
#pragma unroll
    for (int i = 0; i < 8; i++)
#pragma unroll
        for (int j = 0; j < 8; j++) acc[i][j] = 0.f;

    int row0 = (tid >> 4) * 8;
    int col0 = (tid & 15) * 8;

    for (int k0 = 0; k0 < K; k0 += 8) {
#pragma unroll
        for (int i = 0; i < 4; i++) {
            int k = k0 + akq + i;
            As[akq + i][arow] = (k < K) ? A[abase + k] : 0.f;
        }
#pragma unroll
        for (int i = 0; i < 4; i++) {
            int c = n0 + bc + i;
            int k = k0 + brow;
            Bs[brow][bc + i] = (k < K && c < N) ? Bw[(size_t)k * N + c] : 0.f;
        }
        __syncthreads();
#pragma unroll
        for (int kk = 0; kk < 8; kk++) {
            float a[8], b[8];
            *(float4*)(a)     = *(const float4*)&As[kk][row0];
            *(float4*)(a + 4) = *(const float4*)&As[kk][row0 + 4];
            *(float4*)(b)     = *(const float4*)&Bs[kk][col0];
            *(float4*)(b + 4) = *(const float4*)&Bs[kk][col0 + 4];
#pragma unroll
            for (int i = 0; i < 8; i++)
#pragma unroll
                for (int j = 0; j < 8; j++) acc[i][j] = fmaf(a[i], b[j], acc[i][j]);
        }
        __syncthreads();
    }

#pragma unroll
    for (int i = 0; i < 8; i++) {
        int m = m0 + row0 + i;
        float pwv = PWM ? d_pw[m] : 1.f;
        size_t obase;
        if (PADOUT) {
            int bb = m >> 8, ss = m & 255;
            obase = ((size_t)(bb * SP + ss + 1)) * Cc;
        } else {
            obase = (size_t)m * N;
        }
#pragma unroll
        for (int j = 0; j < 8; j++) {
            int c = n0 + col0 + j;
            if (c < N) {
                float v = acc[i][j] + bias[c];
                if (RELU) v = fmaxf(v, 0.f);
                if (PWM)  v *= pwv;
                Cout[obase + c] = v;
            }
        }
    }
}

// ---------------- one LSTM time step (both directions) -------------------------
// grid (19 col-tiles, 8 row-tiles of 64), 256 thr. Col space = j*4+g interleaved.
__global__ __launch_bounds__(256, 2)
void lstm_step(int t) {
    __shared__ float As[8][64];
    __shared__ float Bs[8][64];
    int tid = threadIdx.x;
    int jt = blockIdx.x, rt = blockIdx.y;
    int row0 = rt * 64;
    bool bwd = (row0 >= 256);
    const float* Wt = bwd ? d_Whhb_t : d_Whhf_t;
    const float* xg = bwd ? d_xg_b : d_xg_f;
    const float* hp = d_h + (size_t)(t & 1) * (512 * Hx);
    float*       hn = d_h + (size_t)((t + 1) & 1) * (512 * Hx);
    int col0 = jt * 64;

    float acc[4][4];
#pragma unroll
    for (int i = 0; i < 4; i++)
#pragma unroll
        for (int j = 0; j < 4; j++) acc[i][j] = 0.f;

    int lr = tid & 63;
    int lk = (tid >> 6) * 2;     // 0,2,4,6
    int r0 = (tid >> 4) * 4;
    int c0 = (tid & 15) * 4;

    for (int k0 = 0; k0 < Hx; k0 += 8) {
#pragma unroll
        for (int q = 0; q < 2; q++) {
            int k = k0 + lk + q;
            As[lk + q][lr] = (k < Hx) ? hp[(size_t)(row0 + lr) * Hx + k] : 0.f;
            int cc = col0 + lr;
            Bs[lk + q][lr] = (k < Hx && cc < G4) ? Wt[(size_t)k * G4 + cc] : 0.f;
        }
        __syncthreads();
#pragma unroll
        for (int kk = 0; kk < 8; kk++) {
            float a[4], b[4];
            *(float4*)a = *(const float4*)&As[kk][r0];
            *(float4*)b = *(const float4*)&Bs[kk][c0];
#pragma unroll
            for (int i = 0; i < 4; i++)
#pragma unroll
                for (int j = 0; j < 4; j++) acc[i][j] = fmaf(a[i], b[j], acc[i][j]);
        }
        __syncthreads();
    }

    int j = (col0 + c0) >> 2;
    if (j < Hx) {
#pragma unroll
        for (int i = 0; i < 4; i++) {
            int r = row0 + r0 + i;
            int b = r & 255;
            int Lb = d_L[b];
            int tsrc = bwd ? ((t < Lb) ? (Lb - 1 - t) : t) : t;
            const float* xgp = xg + ((size_t)(b * Sx + tsrc)) * G4 + j * 4;
            float gi = acc[i][0] + xgp[0];
            float gf = acc[i][1] + xgp[1];
            float gg = acc[i][2] + xgp[2];
            float go = acc[i][3] + xgp[3];
            float si = 1.f / (1.f + expf(-gi));
            float sf = 1.f / (1.f + expf(-gf));
            float so = 1.f / (1.f + expf(-go));
            float cn = sf * d_c[(size_t)r * Hx + j] + si * tanhf(gg);
            d_c[(size_t)r * Hx + j] = cn;
            float h = so * tanhf(cn);
            hn[(size_t)r * Hx + j] = h;
            float val = (t < Lb) ? h : 0.f;
            int pos = bwd ? tsrc : t;
            d_to[((size_t)(b * Sx + pos)) * Cc + (bwd ? Hx : 0) + j] = val;
        }
    }
}

// ---------------- build conv1 input (text_out * pw, padded layout) -------------
__global__ void k_xin1() {
    int stride = gridDim.x * blockDim.x;
    for (int idx = blockIdx.x * blockDim.x + threadIdx.x; idx < Mx * Cc; idx += stride) {
        int m = idx / Cc, c = idx - m * Cc;
        int bb = m >> 8, ss = m & 255;
        d_xin1[((size_t)(bb * SP + ss + 1)) * Cc + c] = d_to[idx] * d_pw[m];
    }
}

// ---------------- v[b,c] = sum over aspect rows of relu(conv2) -----------------
__global__ void k_vsum() {
    int b = blockIdx.x;
    int le = d_left[b], a = d_asp[b];
    for (int c = threadIdx.x; c < Cc; c += blockDim.x) {
        float s = 0.f;
        for (int q = 0; q < a; q++)
            s += d_y2[((size_t)(b * Sx + le + q)) * Cc + c];
        d_v[b * Cc + c] = s;
    }
}

// ---------------- logits[b,t] = v . text_out[b,t] ------------------------------
__global__ void k_logits() {
    int b = blockIdx.x;
    int w = threadIdx.x >> 5, lane = threadIdx.x & 31;
    int t = blockIdx.y * 8 + w;
    const float* vb = d_v + (size_t)b * Cc;
    const float* to = d_to + ((size_t)(b * Sx + t)) * Cc;
    float s = 0.f;
    for (int c = lane; c < Cc; c += 32) s = fmaf(vb[c], to[c], s);
#pragma unroll
    for (int o = 16; o; o >>= 1) s += __shfl_xor_sync(0xFFFFFFFFu, s, o);
    if (lane == 0) d_logits[b * Sx + t] = s;
}

// ---------------- softmax + feat + fc ------------------------------------------
__global__ void k_final(const float* __restrict__ fcw, const float* __restrict__ fcb,
                        float* __restrict__ out) {
    __shared__ float sred[256];
    __shared__ float salpha[256];
    __shared__ float feat[Cc];
    int b = blockIdx.x, t = threadIdx.x;
    float lg = d_logits[b * Sx + t];
    sred[t] = lg;
    __syncthreads();
    for (int o = 128; o; o >>= 1) { if (t < o) sred[t] = fmaxf(sred[t], sred[t + o]); __syncthreads(); }
    float mx = sred[0];
    __syncthreads();
    float e = expf(lg - mx);
    salpha[t] = e;
    sred[t] = e;
    __syncthreads();
    for (int o = 128; o; o >>= 1) { if (t < o) sred[t] += sred[t + o]; __syncthreads(); }
    float Z = sred[0];
    __syncthreads();
    for (int c = t; c < Cc; c += 256) {
        float f = 0.f;
        for (int tt = 0; tt < Sx; tt++)
            f = fmaf(salpha[tt], d_to[((size_t)(b * Sx + tt)) * Cc + c], f);
        feat[c] = f / Z;
    }
    __syncthreads();
    for (int p = 0; p < 3; p++) {
        float part = 0.f;
        for (int c = t; c < Cc; c += 256) part = fmaf(feat[c], fcw[p * Cc + c], part);
        sred[t] = part;
        __syncthreads();
        for (int o = 128; o; o >>= 1) { if (t < o) sred[t] += sred[t + o]; __syncthreads(); }
        if (t == 0) out[b * 3 + p] = sred[0] + fcb[p];
        __syncthreads();
    }
}

// ---------------- launch -------------------------------------------------------
extern "C" void kernel_launch(void* const* d_in, const int* in_sizes, int n_in,
                              void* d_out, int out_size) {
    (void)in_sizes; (void)n_in; (void)out_size;
    const int*   cat   = (const int*)d_in[0];
    const int*   aspi  = (const int*)d_in[1];
    const int*   lefti = (const int*)d_in[2];
    const float* emb   = (const float*)d_in[3];
    const float* Wihf  = (const float*)d_in[4];
    const float* Whhf  = (const float*)d_in[5];
    const float* bf    = (const float*)d_in[6];
    const float* Wihb  = (const float*)d_in[7];
    const float* Whhb  = (const float*)d_in[8];
    const float* bbv   = (const float*)d_in[9];
    const float* c1w   = (const float*)d_in[10];
    const float* c1b   = (const float*)d_in[11];
    const float* c2w   = (const float*)d_in[12];
    const float* c2b   = (const float*)d_in[13];
    const float* fcw   = (const float*)d_in[14];
    const float* fcb   = (const float*)d_in[15];
    float* out = (float*)d_out;

    k_meta<<<Bx, 256>>>(cat, aspi, lefti);
    k_zero<<<512, 256>>>();
    k_prep<<<2048, 256>>>(Wihf, Whhf, bf, Wihb, Whhb, bbv, c1w, c2w);
    k_embed<<<4096, 256>>>(cat, emb);

    dim3 g1(10, 512);
    sgemm<0><<<g1, 256>>>(nullptr);
    sgemm<1><<<g1, 256>>>(nullptr);

    dim3 gs(19, 8);
    for (int t = 0; t < Sx; t++) lstm_step<<<gs, 256>>>(t);

    k_xin1<<<4096, 256>>>();

    dim3 g2(5, 512);
    sgemm<2><<<g2, 256>>>(c1b);
    sgemm<3><<<g2, 256>>>(c2b);

    k_vsum<<<Bx, 256>>>();
    dim3 g3(Bx, 32);
    k_logits<<<g3, 256>>>();
    k_final<<<Bx, 256>>>(fcw, fcb, out);
}

// round 5
// speedup vs baseline: 1.5657x; 1.5657x over previous
#include <cuda_runtime.h>
#include <stdint.h>
#include <math.h>

#define Bx 256
#define Sx 256
#define Ex 300
#define Hx 300
#define G4 1200     // 4*H
#define Cc 600      // 2*H channels
#define SP 258      // S + 2 (padded rows for conv)
#define Mx 65536    // B*S
#define KCONV 1800  // 3*Cc

// ---------------- scratch (__device__ globals; zero-init at load) -------------
__device__ float d_text[(size_t)Mx * Ex];       // embeddings [B*S, E]
__device__ float d_xg_f[(size_t)Mx * G4];       // input-gate precompute fwd (gate-interleaved cols)
__device__ float d_xg_b[(size_t)Mx * G4];       // same for bwd weights (on UNreversed text)
__device__ float d_to[(size_t)Mx * Cc];         // text_out [B,S,2H] (masked)
__device__ float d_xin1[(size_t)Bx * SP * Cc];  // conv1 input, padded rows (pads stay 0)
__device__ float d_xin2[(size_t)Bx * SP * Cc];  // conv2 input, padded rows
__device__ float d_y2[(size_t)Mx * Cc];         // relu(conv2)
__device__ float d_h[2 * 512 * Hx];             // h ping-pong, rows: 0..255 fwd, 256..511 bwd
__device__ float d_c[512 * Hx];                 // cell state
__device__ float d_Wihf_t[Ex * G4];             // [k][j*4+g]
__device__ float d_Wihb_t[Ex * G4];
__device__ float d_Whhf_t[Hx * G4];
__device__ float d_Whhb_t[Hx * G4];
__device__ float d_bif[G4];
__device__ float d_bib[G4];
__device__ float d_cw1[KCONV * Cc];             // [(k*600+i)][o]
__device__ float d_cw2[KCONV * Cc];
__device__ float d_pw[Mx];
__device__ int   d_L[Bx], d_asp[Bx], d_left[Bx];
__device__ float d_v[Bx * Cc];
__device__ float d_logits[Mx];

__device__ __forceinline__ float to_tf32(float x) {
    uint32_t r;
    asm("cvt.rna.tf32.f32 %0, %1;" : "=r"(r) : "f"(x));
    return __uint_as_float(r);
}

// ---------------- meta: lengths + position weights ---------------------------
__global__ void k_meta(const int* __restrict__ cat, const int* __restrict__ aspi,
                       const int* __restrict__ lefti) {
    __shared__ int s[3];
    int b = blockIdx.x, t = threadIdx.x;
    if (t < 3) s[t] = 0;
    __syncthreads();
    if (cat[b * Sx + t] != 0) atomicAdd(&s[0], 1);
    if (t < 16 && aspi[b * 16 + t] != 0) atomicAdd(&s[1], 1);
    if (t < 128 && lefti[b * 128 + t] != 0) atomicAdd(&s[2], 1);
    __syncthreads();
    int L = s[0], A = s[1], Le = s[2];
    if (t == 0) { d_L[b] = L; d_asp[b] = A; d_left[b] = Le; }
    float na = (float)(L - A);
    int right = Le + A - 1;
    float w;
    if (t < Le)           w = 1.0f - (float)(Le - t) / na;
    else if (t <= right)  w = 0.0f;
    else if (t < L)       w = 1.0f - (float)(t - right) / na;
    else                  w = 0.0f;
    d_pw[b * Sx + t] = w;
}

// ---------------- zero LSTM state each invocation -----------------------------
__global__ void k_zero() {
    int stride = gridDim.x * blockDim.x;
    for (int i = blockIdx.x * blockDim.x + threadIdx.x; i < 2 * 512 * Hx; i += stride)
        d_h[i] = 0.f;
    for (int i = blockIdx.x * blockDim.x + threadIdx.x; i < 512 * Hx; i += stride)
        d_c[i] = 0.f;
}

// ---------------- weight reshapes ---------------------------------------------
__global__ void k_prep(const float* __restrict__ Wihf, const float* __restrict__ Whhf,
                       const float* __restrict__ bf,
                       const float* __restrict__ Wihb, const float* __restrict__ Whhb,
                       const float* __restrict__ bbv,
                       const float* __restrict__ c1w, const float* __restrict__ c2w) {
    int stride = gridDim.x * blockDim.x;
    int tid0 = blockIdx.x * blockDim.x + threadIdx.x;
    for (int idx = tid0; idx < Ex * G4; idx += stride) {
        int k = idx / G4, col = idx - k * G4;
        int j = col >> 2, g = col & 3;
        int src = (g * Hx + j) * Ex + k;   // Ex == Hx == 300
        d_Wihf_t[idx] = Wihf[src];
        d_Wihb_t[idx] = Wihb[src];
        d_Whhf_t[idx] = Whhf[src];
        d_Whhb_t[idx] = Whhb[src];
    }
    for (int idx = tid0; idx < G4; idx += stride) {
        int j = idx >> 2, g = idx & 3;
        d_bif[idx] = bf[g * Hx + j];
        d_bib[idx] = bbv[g * Hx + j];
    }
    for (int idx = tid0; idx < KCONV * Cc; idx += stride) {
        int o = idx % Cc, r = idx / Cc;
        int kk = r / Cc, i = r - kk * Cc;
        size_t src = (size_t)o * KCONV + i * 3 + kk;
        d_cw1[idx] = c1w[src];
        d_cw2[idx] = c2w[src];
    }
}

// ---------------- embedding gather --------------------------------------------
__global__ void k_embed(const int* __restrict__ cat, const float* __restrict__ emb) {
    int stride = gridDim.x * blockDim.x;
    for (int idx = blockIdx.x * blockDim.x + threadIdx.x; idx < Mx * (Ex / 4); idx += stride) {
        int m = idx / (Ex / 4), e4 = idx - m * (Ex / 4);
        *(float4*)&d_text[(size_t)m * Ex + e4 * 4] =
            *(const float4*)&emb[(size_t)cat[m] * Ex + e4 * 4];
    }
}

// ---------------- tf32 tensor-core GEMM, 128x128 block, BK=16 ------------------
// CFG 0: xg_f  (A=text,  B=Wihf_t, bias=d_bif, N=1200, K=300)
// CFG 1: xg_b  (A=text,  B=Wihb_t, bias=d_bib, N=1200, K=300)
// CFG 2: conv1 (A=xin1 padded windows, B=cw1, bias=ext, relu, *pw, out padded xin2)
// CFG 3: conv2 (A=xin2 padded windows, B=cw2, bias=ext, relu, out y2)
#define LDSW 136
template <int CFG>
__global__ __launch_bounds__(256, 2)
void tgemm(const float* __restrict__ extbias) {
    constexpr int  N      = (CFG < 2) ? G4 : Cc;
    constexpr int  K      = (CFG < 2) ? Ex : KCONV;
    constexpr bool CONVA  = (CFG >= 2);
    constexpr bool RELU   = (CFG >= 2);
    constexpr bool PWM    = (CFG == 2);
    constexpr bool PADOUT = (CFG == 2);
    constexpr int  BK     = 16;

    const float* A    = (CFG < 2) ? d_text : (CFG == 2 ? d_xin1 : d_xin2);
    const float* Bw   = (CFG == 0) ? d_Wihf_t : (CFG == 1) ? d_Wihb_t
                        : (CFG == 2) ? d_cw1 : d_cw2;
    const float* bias = (CFG == 0) ? d_bif : (CFG == 1) ? d_bib : extbias;
    float*       Cout = (CFG == 0) ? d_xg_f : (CFG == 1) ? d_xg_b
                        : (CFG == 2) ? d_xin2 : d_y2;

    __shared__ float As[2][BK][LDSW];
    __shared__ float Bs[2][BK][LDSW];

    int tid = threadIdx.x;
    int lane = tid & 31, wid = tid >> 5;
    int wm = (wid & 1) * 64;       // warp m-offset (2 warps in m)
    int wn = (wid >> 1) * 32;      // warp n-offset (4 warps in n)
    int m0 = blockIdx.y * 128, n0 = blockIdx.x * 128;

    // --- loader indexing (2 float4 per thread for each of A, B) ---
    size_t abase[2]; int arow[2], akq[2];
    int bkr[2], bnq[2];
#pragma unroll
    for (int q = 0; q < 2; q++) {
        int pos = tid + 256 * q;
        arow[q] = pos >> 2;
        akq[q]  = (pos & 3) * 4;
        int m_a = m0 + arow[q];
        if (CONVA) { int bb = m_a >> 8, ss = m_a & 255; abase[q] = ((size_t)(bb * SP + ss)) * Cc; }
        else       abase[q] = (size_t)m_a * K;
        bkr[q] = pos >> 5;
        bnq[q] = (pos & 31) * 4;
    }

    float4 ra[2], rb[2];
    auto load_tiles = [&](int k0) {
#pragma unroll
        for (int q = 0; q < 2; q++) {
            int k = k0 + akq[q];
            ra[q] = (k < K) ? *(const float4*)(A + abase[q] + k)
                            : make_float4(0.f, 0.f, 0.f, 0.f);
            int kb = k0 + bkr[q], n = n0 + bnq[q];
            rb[q] = (kb < K && n < N) ? *(const float4*)(Bw + (size_t)kb * N + n)
                                      : make_float4(0.f, 0.f, 0.f, 0.f);
        }
    };
    auto store_tiles = [&](int s) {
#pragma unroll
        for (int q = 0; q < 2; q++) {
            As[s][akq[q] + 0][arow[q]] = to_tf32(ra[q].x);
            As[s][akq[q] + 1][arow[q]] = to_tf32(ra[q].y);
            As[s][akq[q] + 2][arow[q]] = to_tf32(ra[q].z);
            As[s][akq[q] + 3][arow[q]] = to_tf32(ra[q].w);
            Bs[s][bkr[q]][bnq[q] + 0] = to_tf32(rb[q].x);
            Bs[s][bkr[q]][bnq[q] + 1] = to_tf32(rb[q].y);
            Bs[s][bkr[q]][bnq[q] + 2] = to_tf32(rb[q].z);
            Bs[s][bkr[q]][bnq[q] + 3] = to_tf32(rb[q].w);
        }
    };

    float acc[4][4][4];
#pragma unroll
    for (int i = 0; i < 4; i++)
#pragma unroll
        for (int j = 0; j < 4; j++)
#pragma unroll
            for (int q = 0; q < 4; q++) acc[i][j][q] = 0.f;

    int r = lane >> 2, c = lane & 3;

    auto compute = [&](int s) {
#pragma unroll
        for (int ks = 0; ks < 2; ks++) {
            int kb = ks * 8;
            uint32_t af[4][4], bf[4][2];
#pragma unroll
            for (int mt = 0; mt < 4; mt++) {
                int mb = wm + mt * 16 + r;
                af[mt][0] = __float_as_uint(As[s][kb + c][mb]);
                af[mt][1] = __float_as_uint(As[s][kb + c][mb + 8]);
                af[mt][2] = __float_as_uint(As[s][kb + c + 4][mb]);
                af[mt][3] = __float_as_uint(As[s][kb + c + 4][mb + 8]);
            }
#pragma unroll
            for (int nt = 0; nt < 4; nt++) {
                int nb = wn + nt * 8 + r;
                bf[nt][0] = __float_as_uint(Bs[s][kb + c][nb]);
                bf[nt][1] = __float_as_uint(Bs[s][kb + c + 4][nb]);
            }
#pragma unroll
            for (int mt = 0; mt < 4; mt++)
#pragma unroll
                for (int nt = 0; nt < 4; nt++) {
                    asm volatile(
                        "mma.sync.aligned.m16n8k8.row.col.f32.tf32.tf32.f32 "
                        "{%0,%1,%2,%3}, {%4,%5,%6,%7}, {%8,%9}, {%0,%1,%2,%3};"
                        : "+f"(acc[mt][nt][0]), "+f"(acc[mt][nt][1]),
                          "+f"(acc[mt][nt][2]), "+f"(acc[mt][nt][3])
                        : "r"(af[mt][0]), "r"(af[mt][1]), "r"(af[mt][2]), "r"(af[mt][3]),
                          "r"(bf[nt][0]), "r"(bf[nt][1]));
                }
        }
    };

    constexpr int NK = (K + BK - 1) / BK;
    load_tiles(0);
    store_tiles(0);
    __syncthreads();
    for (int it = 0; it < NK; it++) {
        if (it + 1 < NK) load_tiles((it + 1) * BK);
        compute(it & 1);
        if (it + 1 < NK) store_tiles((it + 1) & 1);
        __syncthreads();
    }

    // epilogue
#pragma unroll
    for (int mt = 0; mt < 4; mt++) {
#pragma unroll
        for (int j2 = 0; j2 < 2; j2++) {
            int m = m0 + wm + mt * 16 + r + j2 * 8;
            float pwv = PWM ? d_pw[m] : 1.f;
            size_t obase;
            if (PADOUT) { int bb = m >> 8, ss = m & 255; obase = ((size_t)(bb * SP + ss + 1)) * Cc; }
            else        obase = (size_t)m * N;
#pragma unroll
            for (int nt = 0; nt < 4; nt++) {
                int n = n0 + wn + nt * 8 + c * 2;
#pragma unroll
                for (int jj = 0; jj < 2; jj++) {
                    if (n + jj < N) {
                        float v = acc[mt][nt][j2 * 2 + jj] + bias[n + jj];
                        if (RELU) v = fmaxf(v, 0.f);
                        if (PWM)  v *= pwv;
                        Cout[obase + n + jj] = v;
                    }
                }
            }
        }
    }
}

// ---------------- one LSTM time step (both directions) -------------------------
__global__ __launch_bounds__(256, 2)
void lstm_step(int t) {
    __shared__ float As[8][64];
    __shared__ float Bs[8][64];
    int tid = threadIdx.x;
    int jt = blockIdx.x, rt = blockIdx.y;
    int row0 = rt * 64;
    bool bwd = (row0 >= 256);
    const float* Wt = bwd ? d_Whhb_t : d_Whhf_t;
    const float* xg = bwd ? d_xg_b : d_xg_f;
    const float* hp = d_h + (size_t)(t & 1) * (512 * Hx);
    float*       hn = d_h + (size_t)((t + 1) & 1) * (512 * Hx);
    int col0 = jt * 64;

    float acc[4][4];
#pragma unroll
    for (int i = 0; i < 4; i++)
#pragma unroll
        for (int j = 0; j < 4; j++) acc[i][j] = 0.f;

    int lr = tid & 63;
    int lk = (tid >> 6) * 2;
    int r0 = (tid >> 4) * 4;
    int c0 = (tid & 15) * 4;

    for (int k0 = 0; k0 < Hx; k0 += 8) {
#pragma unroll
        for (int q = 0; q < 2; q++) {
            int k = k0 + lk + q;
            As[lk + q][lr] = (k < Hx) ? hp[(size_t)(row0 + lr) * Hx + k] : 0.f;
            int cc = col0 + lr;
            Bs[lk + q][lr] = (k < Hx && cc < G4) ? Wt[(size_t)k * G4 + cc] : 0.f;
        }
        __syncthreads();
#pragma unroll
        for (int kk = 0; kk < 8; kk++) {
            float a[4], b[4];
            *(float4*)a = *(const float4*)&As[kk][r0];
            *(float4*)b = *(const float4*)&Bs[kk][c0];
#pragma unroll
            for (int i = 0; i < 4; i++)
#pragma unroll
                for (int j = 0; j < 4; j++) acc[i][j] = fmaf(a[i], b[j], acc[i][j]);
        }
        __syncthreads();
    }

    int j = (col0 + c0) >> 2;
    if (j < Hx) {
#pragma unroll
        for (int i = 0; i < 4; i++) {
            int rr = row0 + r0 + i;
            int b = rr & 255;
            int Lb = d_L[b];
            int tsrc = bwd ? ((t < Lb) ? (Lb - 1 - t) : t) : t;
            const float* xgp = xg + ((size_t)(b * Sx + tsrc)) * G4 + j * 4;
            float gi = acc[i][0] + xgp[0];
            float gf = acc[i][1] + xgp[1];
            float gg = acc[i][2] + xgp[2];
            float go = acc[i][3] + xgp[3];
            float si = 1.f / (1.f + expf(-gi));
            float sf = 1.f / (1.f + expf(-gf));
            float so = 1.f / (1.f + expf(-go));
            float cn = sf * d_c[(size_t)rr * Hx + j] + si * tanhf(gg);
            d_c[(size_t)rr * Hx + j] = cn;
            float h = so * tanhf(cn);
            hn[(size_t)rr * Hx + j] = h;
            float val = (t < Lb) ? h : 0.f;
            int pos = bwd ? tsrc : t;
            d_to[((size_t)(b * Sx + pos)) * Cc + (bwd ? Hx : 0) + j] = val;
        }
    }
}

// ---------------- build conv1 input (text_out * pw, padded layout) -------------
__global__ void k_xin1() {
    int stride = gridDim.x * blockDim.x;
    for (int idx = blockIdx.x * blockDim.x + threadIdx.x; idx < Mx * Cc; idx += stride) {
        int m = idx / Cc, c = idx - m * Cc;
        int bb = m >> 8, ss = m & 255;
        d_xin1[((size_t)(bb * SP + ss + 1)) * Cc + c] = d_to[idx] * d_pw[m];
    }
}

// ---------------- v[b,c] = sum over aspect rows of relu(conv2) -----------------
__global__ void k_vsum() {
    int b = blockIdx.x;
    int le = d_left[b], a = d_asp[b];
    for (int c = threadIdx.x; c < Cc; c += blockDim.x) {
        float s = 0.f;
        for (int q = 0; q < a; q++)
            s += d_y2[((size_t)(b * Sx + le + q)) * Cc + c];
        d_v[b * Cc + c] = s;
    }
}

// ---------------- logits[b,t] = v . text_out[b,t] ------------------------------
__global__ void k_logits() {
    int b = blockIdx.x;
    int w = threadIdx.x >> 5, lane = threadIdx.x & 31;
    int t = blockIdx.y * 8 + w;
    const float* vb = d_v + (size_t)b * Cc;
    const float* to = d_to + ((size_t)(b * Sx + t)) * Cc;
    float s = 0.f;
    for (int c = lane; c < Cc; c += 32) s = fmaf(vb[c], to[c], s);
#pragma unroll
    for (int o = 16; o; o >>= 1) s += __shfl_xor_sync(0xFFFFFFFFu, s, o);
    if (lane == 0) d_logits[b * Sx + t] = s;
}

// ---------------- softmax + feat + fc ------------------------------------------
__global__ void k_final(const float* __restrict__ fcw, const float* __restrict__ fcb,
                        float* __restrict__ out) {
    __shared__ float sred[256];
    __shared__ float salpha[256];
    __shared__ float feat[Cc];
    int b = blockIdx.x, t = threadIdx.x;
    float lg = d_logits[b * Sx + t];
    sred[t] = lg;
    __syncthreads();
    for (int o = 128; o; o >>= 1) { if (t < o) sred[t] = fmaxf(sred[t], sred[t + o]); __syncthreads(); }
    float mx = sred[0];
    __syncthreads();
    float e = expf(lg - mx);
    salpha[t] = e;
    sred[t] = e;
    __syncthreads();
    for (int o = 128; o; o >>= 1) { if (t < o) sred[t] += sred[t + o]; __syncthreads(); }
    float Z = sred[0];
    __syncthreads();
    for (int c = t; c < Cc; c += 256) {
        float f = 0.f;
        for (int tt = 0; tt < Sx; tt++)
            f = fmaf(salpha[tt], d_to[((size_t)(b * Sx + tt)) * Cc + c], f);
        feat[c] = f / Z;
    }
    __syncthreads();
    for (int p = 0; p < 3; p++) {
        float part = 0.f;
        for (int c = t; c < Cc; c += 256) part = fmaf(feat[c], fcw[p * Cc + c], part);
        sred[t] = part;
        __syncthreads();
        for (int o = 128; o; o >>= 1) { if (t < o) sred[t] += sred[t + o]; __syncthreads(); }
        if (t == 0) out[b * 3 + p] = sred[0] + fcb[p];
        __syncthreads();
    }
}

// ---------------- launch -------------------------------------------------------
extern "C" void kernel_launch(void* const* d_in, const int* in_sizes, int n_in,
                              void* d_out, int out_size) {
    (void)in_sizes; (void)n_in; (void)out_size;
    const int*   cat   = (const int*)d_in[0];
    const int*   aspi  = (const int*)d_in[1];
    const int*   lefti = (const int*)d_in[2];
    const float* emb   = (const float*)d_in[3];
    const float* Wihf  = (const float*)d_in[4];
    const float* Whhf  = (const float*)d_in[5];
    const float* bf    = (const float*)d_in[6];
    const float* Wihb  = (const float*)d_in[7];
    const float* Whhb  = (const float*)d_in[8];
    const float* bbv   = (const float*)d_in[9];
    const float* c1w   = (const float*)d_in[10];
    const float* c1b   = (const float*)d_in[11];
    const float* c2w   = (const float*)d_in[12];
    const float* c2b   = (const float*)d_in[13];
    const float* fcw   = (const float*)d_in[14];
    const float* fcb   = (const float*)d_in[15];
    float* out = (float*)d_out;

    k_meta<<<Bx, 256>>>(cat, aspi, lefti);
    k_zero<<<512, 256>>>();
    k_prep<<<2048, 256>>>(Wihf, Whhf, bf, Wihb, Whhb, bbv, c1w, c2w);
    k_embed<<<4096, 256>>>(cat, emb);

    dim3 g1(10, 512);   // N=1200 -> 10 col tiles
    tgemm<0><<<g1, 256>>>(nullptr);
    tgemm<1><<<g1, 256>>>(nullptr);

    dim3 gs(19, 8);
    for (int t = 0; t < Sx; t++) lstm_step<<<gs, 256>>>(t);

    k_xin1<<<4096, 256>>>();

    dim3 g2(5, 512);    // N=600 -> 5 col tiles
    tgemm<2><<<g2, 256>>>(c1b);
    tgemm<3><<<g2, 256>>>(c2b);

    k_vsum<<<Bx, 256>>>();
    dim3 g3(Bx, 32);
    k_logits<<<g3, 256>>>();
    k_final<<<Bx, 256>>>(fcw, fcb, out);
}

// round 6
// speedup vs baseline: 1.8634x; 1.1902x over previous
#include <cuda_runtime.h>
#include <stdint.h>
#include <math.h>

#define Bx 256
#define Sx 256
#define Ex 300
#define Hx 300
#define G4 1200     // 4*H
#define Cc 600      // 2*H channels
#define Mx 65536    // B*S
#define KCONV 1800  // 3*Cc

// ---------------- scratch (__device__ globals; zero-init at load) -------------
__device__ float d_text[(size_t)Mx * Ex];       // embeddings [B*S, E]
__device__ float d_xg_f[(size_t)Mx * G4];       // input-gate precompute fwd (gate-interleaved cols)
__device__ float d_xg_b[(size_t)Mx * G4];       // same for bwd weights (on UNreversed text)
__device__ float d_to[(size_t)Mx * Cc];         // text_out [B,S,2H] (masked)
__device__ float d_h[2 * 512 * Hx];             // h ping-pong, rows: 0..255 fwd, 256..511 bwd
__device__ float d_c[512 * Hx];                 // cell state
__device__ float d_Wihf_t[Ex * G4];             // [k][j*4+g]
__device__ float d_Wihb_t[Ex * G4];
__device__ float d_Whhf_t[Hx * G4];
__device__ float d_Whhb_t[Hx * G4];
__device__ float d_bif[G4];
__device__ float d_bib[G4];
__device__ float d_cw1[KCONV * Cc];             // [(dk*600+i)][o]
__device__ float d_cw2[KCONV * Cc];
__device__ float d_pw[Mx];
__device__ int   d_L[Bx], d_asp[Bx], d_left[Bx];
__device__ float d_ca[512 * KCONV];             // conv1 input windows, 2 rows per batch
__device__ float d_x2row[512 * Cc];             // conv2 nonzero input rows (xin2 at left-1 / right+1)
__device__ float d_rowscale[512];               // pw at output row (or 0 if invalid)
__device__ float d_v[Bx * Cc];
__device__ float d_logits[Mx];

__device__ __forceinline__ float to_tf32(float x) {
    uint32_t r;
    asm("cvt.rna.tf32.f32 %0, %1;" : "=r"(r) : "f"(x));
    return __uint_as_float(r);
}

// ---------------- meta: lengths + position weights ---------------------------
__global__ void k_meta(const int* __restrict__ cat, const int* __restrict__ aspi,
                       const int* __restrict__ lefti) {
    __shared__ int s[3];
    int b = blockIdx.x, t = threadIdx.x;
    if (t < 3) s[t] = 0;
    __syncthreads();
    if (cat[b * Sx + t] != 0) atomicAdd(&s[0], 1);
    if (t < 16 && aspi[b * 16 + t] != 0) atomicAdd(&s[1], 1);
    if (t < 128 && lefti[b * 128 + t] != 0) atomicAdd(&s[2], 1);
    __syncthreads();
    int L = s[0], A = s[1], Le = s[2];
    if (t == 0) { d_L[b] = L; d_asp[b] = A; d_left[b] = Le; }
    float na = (float)(L - A);
    int right = Le + A - 1;
    float w;
    if (t < Le)           w = 1.0f - (float)(Le - t) / na;
    else if (t <= right)  w = 0.0f;
    else if (t < L)       w = 1.0f - (float)(t - right) / na;
    else                  w = 0.0f;
    d_pw[b * Sx + t] = w;
}

// ---------------- zero LSTM state each invocation -----------------------------
__global__ void k_zero() {
    int stride = gridDim.x * blockDim.x;
    for (int i = blockIdx.x * blockDim.x + threadIdx.x; i < 2 * 512 * Hx; i += stride)
        d_h[i] = 0.f;
    for (int i = blockIdx.x * blockDim.x + threadIdx.x; i < 512 * Hx; i += stride)
        d_c[i] = 0.f;
}

// ---------------- weight reshapes ---------------------------------------------
__global__ void k_prep(const float* __restrict__ Wihf, const float* __restrict__ Whhf,
                       const float* __restrict__ bf,
                       const float* __restrict__ Wihb, const float* __restrict__ Whhb,
                       const float* __restrict__ bbv,
                       const float* __restrict__ c1w, const float* __restrict__ c2w) {
    int stride = gridDim.x * blockDim.x;
    int tid0 = blockIdx.x * blockDim.x + threadIdx.x;
    for (int idx = tid0; idx < Ex * G4; idx += stride) {
        int k = idx / G4, col = idx - k * G4;
        int j = col >> 2, g = col & 3;
        int src = (g * Hx + j) * Ex + k;   // Ex == Hx == 300
        d_Wihf_t[idx] = Wihf[src];
        d_Wihb_t[idx] = Wihb[src];
        d_Whhf_t[idx] = Whhf[src];
        d_Whhb_t[idx] = Whhb[src];
    }
    for (int idx = tid0; idx < G4; idx += stride) {
        int j = idx >> 2, g = idx & 3;
        d_bif[idx] = bf[g * Hx + j];
        d_bib[idx] = bbv[g * Hx + j];
    }
    for (int idx = tid0; idx < KCONV * Cc; idx += stride) {
        int o = idx % Cc, r = idx / Cc;
        int kk = r / Cc, i = r - kk * Cc;
        size_t src = (size_t)o * KCONV + i * 3 + kk;
        d_cw1[idx] = c1w[src];
        d_cw2[idx] = c2w[src];
    }
}

// ---------------- embedding gather --------------------------------------------
__global__ void k_embed(const int* __restrict__ cat, const float* __restrict__ emb) {
    int stride = gridDim.x * blockDim.x;
    for (int idx = blockIdx.x * blockDim.x + threadIdx.x; idx < Mx * (Ex / 4); idx += stride) {
        int m = idx / (Ex / 4), e4 = idx - m * (Ex / 4);
        *(float4*)&d_text[(size_t)m * Ex + e4 * 4] =
            *(const float4*)&emb[(size_t)cat[m] * Ex + e4 * 4];
    }
}

// ---------------- tf32 tensor-core GEMM, 128x128 block, BK=16 ------------------
// CFG 0: xg_f   A=d_text [65536x300],  B=Wihf_t [300x1200], +bias
// CFG 1: xg_b   A=d_text,              B=Wihb_t,            +bias
// CFG 4: conv1  A=d_ca   [512x1800],   B=cw1   [1800x600],  +bias, relu, *rowscale
#define LDSW 136
template <int CFG>
__global__ __launch_bounds__(256, 2)
void tgemm(const float* __restrict__ extbias) {
    constexpr int  N     = (CFG < 2) ? G4 : Cc;
    constexpr int  K     = (CFG < 2) ? Ex : KCONV;
    constexpr bool RELU  = (CFG == 4);
    constexpr bool RSCL  = (CFG == 4);
    constexpr int  BK    = 16;

    const float* A    = (CFG < 2) ? d_text : d_ca;
    const float* Bw   = (CFG == 0) ? d_Wihf_t : (CFG == 1) ? d_Wihb_t : d_cw1;
    const float* bias = (CFG == 0) ? d_bif : (CFG == 1) ? d_bib : extbias;
    float*       Cout = (CFG == 0) ? d_xg_f : (CFG == 1) ? d_xg_b : d_x2row;

    __shared__ float As[2][BK][LDSW];
    __shared__ float Bs[2][BK][LDSW];

    int tid = threadIdx.x;
    int lane = tid & 31, wid = tid >> 5;
    int wm = (wid & 1) * 64;
    int wn = (wid >> 1) * 32;
    int m0 = blockIdx.y * 128, n0 = blockIdx.x * 128;

    size_t abase[2]; int arow[2], akq[2];
    int bkr[2], bnq[2];
#pragma unroll
    for (int q = 0; q < 2; q++) {
        int pos = tid + 256 * q;
        arow[q] = pos >> 2;
        akq[q]  = (pos & 3) * 4;
        abase[q] = (size_t)(m0 + arow[q]) * K;
        bkr[q] = pos >> 5;
        bnq[q] = (pos & 31) * 4;
    }

    float4 ra[2], rb[2];
    auto load_tiles = [&](int k0) {
#pragma unroll
        for (int q = 0; q < 2; q++) {
            int k = k0 + akq[q];
            ra[q] = (k < K) ? *(const float4*)(A + abase[q] + k)
                            : make_float4(0.f, 0.f, 0.f, 0.f);
            int kb = k0 + bkr[q], n = n0 + bnq[q];
            rb[q] = (kb < K && n < N) ? *(const float4*)(Bw + (size_t)kb * N + n)
                                      : make_float4(0.f, 0.f, 0.f, 0.f);
        }
    };
    auto store_tiles = [&](int s) {
#pragma unroll
        for (int q = 0; q < 2; q++) {
            As[s][akq[q] + 0][arow[q]] = to_tf32(ra[q].x);
            As[s][akq[q] + 1][arow[q]] = to_tf32(ra[q].y);
            As[s][akq[q] + 2][arow[q]] = to_tf32(ra[q].z);
            As[s][akq[q] + 3][arow[q]] = to_tf32(ra[q].w);
            Bs[s][bkr[q]][bnq[q] + 0] = to_tf32(rb[q].x);
            Bs[s][bkr[q]][bnq[q] + 1] = to_tf32(rb[q].y);
            Bs[s][bkr[q]][bnq[q] + 2] = to_tf32(rb[q].z);
            Bs[s][bkr[q]][bnq[q] + 3] = to_tf32(rb[q].w);
        }
    };

    float acc[4][4][4];
#pragma unroll
    for (int i = 0; i < 4; i++)
#pragma unroll
        for (int j = 0; j < 4; j++)
#pragma unroll
            for (int q = 0; q < 4; q++) acc[i][j][q] = 0.f;

    int r = lane >> 2, c = lane & 3;

    auto compute = [&](int s) {
#pragma unroll
        for (int ks = 0; ks < 2; ks++) {
            int kb = ks * 8;
            uint32_t af[4][4], bf[4][2];
#pragma unroll
            for (int mt = 0; mt < 4; mt++) {
                int mb = wm + mt * 16 + r;
                af[mt][0] = __float_as_uint(As[s][kb + c][mb]);
                af[mt][1] = __float_as_uint(As[s][kb + c][mb + 8]);
                af[mt][2] = __float_as_uint(As[s][kb + c + 4][mb]);
                af[mt][3] = __float_as_uint(As[s][kb + c + 4][mb + 8]);
            }
#pragma unroll
            for (int nt = 0; nt < 4; nt++) {
                int nb = wn + nt * 8 + r;
                bf[nt][0] = __float_as_uint(Bs[s][kb + c][nb]);
                bf[nt][1] = __float_as_uint(Bs[s][kb + c + 4][nb]);
            }
#pragma unroll
            for (int mt = 0; mt < 4; mt++)
#pragma unroll
                for (int nt = 0; nt < 4; nt++) {
                    asm volatile(
                        "mma.sync.aligned.m16n8k8.row.col.f32.tf32.tf32.f32 "
                        "{%0,%1,%2,%3}, {%4,%5,%6,%7}, {%8,%9}, {%0,%1,%2,%3};"
                        : "+f"(acc[mt][nt][0]), "+f"(acc[mt][nt][1]),
                          "+f"(acc[mt][nt][2]), "+f"(acc[mt][nt][3])
                        : "r"(af[mt][0]), "r"(af[mt][1]), "r"(af[mt][2]), "r"(af[mt][3]),
                          "r"(bf[nt][0]), "r"(bf[nt][1]));
                }
        }
    };

    constexpr int NK = (K + BK - 1) / BK;
    load_tiles(0);
    store_tiles(0);
    __syncthreads();
    for (int it = 0; it < NK; it++) {
        if (it + 1 < NK) load_tiles((it + 1) * BK);
        compute(it & 1);
        if (it + 1 < NK) store_tiles((it + 1) & 1);
        __syncthreads();
    }

    // epilogue
#pragma unroll
    for (int mt = 0; mt < 4; mt++) {
#pragma unroll
        for (int j2 = 0; j2 < 2; j2++) {
            int m = m0 + wm + mt * 16 + r + j2 * 8;
            float scl = RSCL ? d_rowscale[m] : 1.f;
            size_t obase = (size_t)m * N;
#pragma unroll
            for (int nt = 0; nt < 4; nt++) {
                int n = n0 + wn + nt * 8 + c * 2;
#pragma unroll
                for (int jj = 0; jj < 2; jj++) {
                    if (n + jj < N) {
                        float v = acc[mt][nt][j2 * 2 + jj] + bias[n + jj];
                        if (RELU) v = fmaxf(v, 0.f);
                        if (RSCL) v *= scl;
                        Cout[obase + n + jj] = v;
                    }
                }
            }
        }
    }
}

// ---------------- one LSTM time step (both directions) -------------------------
__global__ __launch_bounds__(256, 2)
void lstm_step(int t) {
    __shared__ float As[8][64];
    __shared__ float Bs[8][64];
    int tid = threadIdx.x;
    int jt = blockIdx.x, rt = blockIdx.y;
    int row0 = rt * 64;
    bool bwd = (row0 >= 256);
    const float* Wt = bwd ? d_Whhb_t : d_Whhf_t;
    const float* xg = bwd ? d_xg_b : d_xg_f;
    const float* hp = d_h + (size_t)(t & 1) * (512 * Hx);
    float*       hn = d_h + (size_t)((t + 1) & 1) * (512 * Hx);
    int col0 = jt * 64;

    float acc[4][4];
#pragma unroll
    for (int i = 0; i < 4; i++)
#pragma unroll
        for (int j = 0; j < 4; j++) acc[i][j] = 0.f;

    int lr = tid & 63;
    int lk = (tid >> 6) * 2;
    int r0 = (tid >> 4) * 4;
    int c0 = (tid & 15) * 4;

    for (int k0 = 0; k0 < Hx; k0 += 8) {
#pragma unroll
        for (int q = 0; q < 2; q++) {
            int k = k0 + lk + q;
            As[lk + q][lr] = (k < Hx) ? hp[(size_t)(row0 + lr) * Hx + k] : 0.f;
            int cc = col0 + lr;
            Bs[lk + q][lr] = (k < Hx && cc < G4) ? Wt[(size_t)k * G4 + cc] : 0.f;
        }
        __syncthreads();
#pragma unroll
        for (int kk = 0; kk < 8; kk++) {
            float a[4], b[4];
            *(float4*)a = *(const float4*)&As[kk][r0];
            *(float4*)b = *(const float4*)&Bs[kk][c0];
#pragma unroll
            for (int i = 0; i < 4; i++)
#pragma unroll
                for (int j = 0; j < 4; j++) acc[i][j] = fmaf(a[i], b[j], acc[i][j]);
        }
        __syncthreads();
    }

    int j = (col0 + c0) >> 2;
    if (j < Hx) {
#pragma unroll
        for (int i = 0; i < 4; i++) {
            int rr = row0 + r0 + i;
            int b = rr & 255;
            int Lb = d_L[b];
            int tsrc = bwd ? ((t < Lb) ? (Lb - 1 - t) : t) : t;
            const float* xgp = xg + ((size_t)(b * Sx + tsrc)) * G4 + j * 4;
            float gi = acc[i][0] + xgp[0];
            float gf = acc[i][1] + xgp[1];
            float gg = acc[i][2] + xgp[2];
            float go = acc[i][3] + xgp[3];
            float si = 1.f / (1.f + expf(-gi));
            float sf = 1.f / (1.f + expf(-gf));
            float so = 1.f / (1.f + expf(-go));
            float cn = sf * d_c[(size_t)rr * Hx + j] + si * tanhf(gg);
            d_c[(size_t)rr * Hx + j] = cn;
            float h = so * tanhf(cn);
            hn[(size_t)rr * Hx + j] = h;
            float val = (t < Lb) ? h : 0.f;
            int pos = bwd ? tsrc : t;
            d_to[((size_t)(b * Sx + pos)) * Cc + (bwd ? Hx : 0) + j] = val;
        }
    }
}

// ---------------- gather conv1 input windows (2 rows per batch) -----------------
__global__ void k_gatherca() {
    int r = blockIdx.x;            // 0..511
    int b = r >> 1, side = r & 1;
    int le = d_left[b];
    int rt = le + d_asp[b] - 1;
    int p = side ? (rt + 1) : (le - 1);
    bool valid = (p >= 0 && p < Sx);
    if (threadIdx.x == 0)
        d_rowscale[r] = valid ? d_pw[b * Sx + p] : 0.f;
    for (int k = threadIdx.x; k < KCONV; k += blockDim.x) {
        int dk = k / Cc, i = k - dk * Cc;
        int prow = p - 1 + dk;
        float val = 0.f;
        if (valid && prow >= 0 && prow < Sx)
            val = d_to[((size_t)(b * Sx + prow)) * Cc + i] * d_pw[b * Sx + prow];
        d_ca[(size_t)r * KCONV + k] = val;
    }
}

// ---------------- conv2 on the two nonzero rows + v accumulation ----------------
// y2[left]  = relu(W2k0 @ x2row0 + b2)   (asp>=2)
// y2[right] = relu(W2k2 @ x2row1 + b2)   (asp>=2)
// middle rows: relu(b2).  asp==1: relu(W2k0@x2row0 + W2k2@x2row1 + b2).
__global__ void k_vrow(const float* __restrict__ c2bias) {
    __shared__ float s0[Cc], s1[Cc];
    int b = blockIdx.x, tid = threadIdx.x;
    int a = d_asp[b];
    for (int i = tid; i < Cc; i += blockDim.x) {
        s0[i] = d_x2row[(size_t)(b * 2 + 0) * Cc + i];
        s1[i] = d_x2row[(size_t)(b * 2 + 1) * Cc + i];
    }
    __syncthreads();
    float acc0[3] = {0.f, 0.f, 0.f}, acc1[3] = {0.f, 0.f, 0.f};
    for (int i = 0; i < Cc; i++) {
        float a0 = s0[i], a1 = s1[i];
        const float* w0 = d_cw2 + (size_t)i * Cc;            // dk=0 rows
        const float* w2 = d_cw2 + (size_t)(1200 + i) * Cc;   // dk=2 rows
#pragma unroll
        for (int q = 0; q < 3; q++) {
            int o = tid + q * 256;
            if (o < Cc) {
                acc0[q] = fmaf(w0[o], a0, acc0[q]);
                acc1[q] = fmaf(w2[o], a1, acc1[q]);
            }
        }
    }
#pragma unroll
    for (int q = 0; q < 3; q++) {
        int o = tid + q * 256;
        if (o < Cc) {
            float bb = c2bias[o];
            float v;
            if (a == 1) {
                v = fmaxf(acc0[q] + acc1[q] + bb, 0.f);
            } else {
                v = fmaxf(acc0[q] + bb, 0.f) + fmaxf(acc1[q] + bb, 0.f)
                  + (float)(a - 2) * fmaxf(bb, 0.f);
            }
            d_v[b * Cc + o] = v;
        }
    }
}

// ---------------- logits[b,t] = v . text_out[b,t] ------------------------------
__global__ void k_logits() {
    int b = blockIdx.x;
    int w = threadIdx.x >> 5, lane = threadIdx.x & 31;
    int t = blockIdx.y * 8 + w;
    const float* vb = d_v + (size_t)b * Cc;
    const float* to = d_to + ((size_t)(b * Sx + t)) * Cc;
    float s = 0.f;
    for (int c = lane; c < Cc; c += 32) s = fmaf(vb[c], to[c], s);
#pragma unroll
    for (int o = 16; o; o >>= 1) s += __shfl_xor_sync(0xFFFFFFFFu, s, o);
    if (lane == 0) d_logits[b * Sx + t] = s;
}

// ---------------- softmax + feat + fc ------------------------------------------
__global__ void k_final(const float* __restrict__ fcw, const float* __restrict__ fcb,
                        float* __restrict__ out) {
    __shared__ float sred[256];
    __shared__ float salpha[256];
    __shared__ float feat[Cc];
    int b = blockIdx.x, t = threadIdx.x;
    float lg = d_logits[b * Sx + t];
    sred[t] = lg;
    __syncthreads();
    for (int o = 128; o; o >>= 1) { if (t < o) sred[t] = fmaxf(sred[t], sred[t + o]); __syncthreads(); }
    float mx = sred[0];
    __syncthreads();
    float e = expf(lg - mx);
    salpha[t] = e;
    sred[t] = e;
    __syncthreads();
    for (int o = 128; o; o >>= 1) { if (t < o) sred[t] += sred[t + o]; __syncthreads(); }
    float Z = sred[0];
    __syncthreads();
    for (int c = t; c < Cc; c += 256) {
        float f = 0.f;
        for (int tt = 0; tt < Sx; tt++)
            f = fmaf(salpha[tt], d_to[((size_t)(b * Sx + tt)) * Cc + c], f);
        feat[c] = f / Z;
    }
    __syncthreads();
    for (int p = 0; p < 3; p++) {
        float part = 0.f;
        for (int c = t; c < Cc; c += 256) part = fmaf(feat[c], fcw[p * Cc + c], part);
        sred[t] = part;
        __syncthreads();
        for (int o = 128; o; o >>= 1) { if (t < o) sred[t] += sred[t + o]; __syncthreads(); }
        if (t == 0) out[b * 3 + p] = sred[0] + fcb[p];
        __syncthreads();
    }
}

// ---------------- launch -------------------------------------------------------
extern "C" void kernel_launch(void* const* d_in, const int* in_sizes, int n_in,
                              void* d_out, int out_size) {
    (void)in_sizes; (void)n_in; (void)out_size;
    const int*   cat   = (const int*)d_in[0];
    const int*   aspi  = (const int*)d_in[1];
    const int*   lefti = (const int*)d_in[2];
    const float* emb   = (const float*)d_in[3];
    const float* Wihf  = (const float*)d_in[4];
    const float* Whhf  = (const float*)d_in[5];
    const float* bf    = (const float*)d_in[6];
    const float* Wihb  = (const float*)d_in[7];
    const float* Whhb  = (const float*)d_in[8];
    const float* bbv   = (const float*)d_in[9];
    const float* c1w   = (const float*)d_in[10];
    const float* c1b   = (const float*)d_in[11];
    const float* c2w   = (const float*)d_in[12];
    const float* c2b   = (const float*)d_in[13];
    const float* fcw   = (const float*)d_in[14];
    const float* fcb   = (const float*)d_in[15];
    float* out = (float*)d_out;

    k_meta<<<Bx, 256>>>(cat, aspi, lefti);
    k_zero<<<512, 256>>>();
    k_prep<<<2048, 256>>>(Wihf, Whhf, bf, Wihb, Whhb, bbv, c1w, c2w);
    k_embed<<<4096, 256>>>(cat, emb);

    dim3 g1(10, 512);   // N=1200, M=65536
    tgemm<0><<<g1, 256>>>(nullptr);
    tgemm<1><<<g1, 256>>>(nullptr);

    dim3 gs(19, 8);
    for (int t = 0; t < Sx; t++) lstm_step<<<gs, 256>>>(t);

    k_gatherca<<<512, 256>>>();
    dim3 g2(5, 4);      // N=600, M=512
    tgemm<4><<<g2, 256>>>(c1b);
    k_vrow<<<Bx, 256>>>(c2b);

    dim3 g3(Bx, 32);
    k_logits<<<g3, 256>>>();
    k_final<<<Bx, 256>>>(fcw, fcb, out);
}

// round 7
// speedup vs baseline: 4.4893x; 2.4092x over previous
#include <cuda_runtime.h>
#include <stdint.h>
#include <math.h>

#define Bx 256
#define Sx 256
#define Ex 300
#define Hx 300
#define G4 1200     // 4*H
#define Cc 600      // 2*H channels
#define Mx 65536    // B*S
#define KCONV 1800  // 3*Cc
#define NBLK 152    // persistent LSTM grid

// ---------------- scratch (__device__ globals; zero-init at load) -------------
__device__ float d_text[(size_t)Mx * Ex];
__device__ float d_xg_f[(size_t)Mx * G4];
__device__ float d_xg_b[(size_t)Mx * G4];
__device__ float d_to[(size_t)Mx * Cc];
__device__ float d_h[2 * 512 * Hx];             // ping-pong
__device__ float d_Wihf_t[Ex * G4];             // [k][j*4+g]
__device__ float d_Wihb_t[Ex * G4];
__device__ float d_Whhf_t[Hx * G4];
__device__ float d_Whhb_t[Hx * G4];
__device__ float d_bif[G4];
__device__ float d_bib[G4];
__device__ float d_cw1[KCONV * Cc];
__device__ float d_cw2[KCONV * Cc];
__device__ float d_pw[Mx];
__device__ int   d_L[Bx], d_asp[Bx], d_left[Bx];
__device__ float d_ca[512 * KCONV];
__device__ float d_x2row[512 * Cc];
__device__ float d_rowscale[512];
__device__ float d_v[Bx * Cc];
__device__ float d_logits[Mx];
__device__ unsigned d_bar;

__device__ __forceinline__ float to_tf32(float x) {
    uint32_t r;
    asm("cvt.rna.tf32.f32 %0, %1;" : "=r"(r) : "f"(x));
    return __uint_as_float(r);
}

// ---------------- meta ---------------------------------------------------------
__global__ void k_meta(const int* __restrict__ cat, const int* __restrict__ aspi,
                       const int* __restrict__ lefti) {
    __shared__ int s[3];
    int b = blockIdx.x, t = threadIdx.x;
    if (t < 3) s[t] = 0;
    __syncthreads();
    if (cat[b * Sx + t] != 0) atomicAdd(&s[0], 1);
    if (t < 16 && aspi[b * 16 + t] != 0) atomicAdd(&s[1], 1);
    if (t < 128 && lefti[b * 128 + t] != 0) atomicAdd(&s[2], 1);
    __syncthreads();
    int L = s[0], A = s[1], Le = s[2];
    if (t == 0) { d_L[b] = L; d_asp[b] = A; d_left[b] = Le; }
    float na = (float)(L - A);
    int right = Le + A - 1;
    float w;
    if (t < Le)           w = 1.0f - (float)(Le - t) / na;
    else if (t <= right)  w = 0.0f;
    else if (t < L)       w = 1.0f - (float)(t - right) / na;
    else                  w = 0.0f;
    d_pw[b * Sx + t] = w;
}

// ---------------- zero h buffers + barrier counter -----------------------------
__global__ void k_zero() {
    int stride = gridDim.x * blockDim.x;
    int tid0 = blockIdx.x * blockDim.x + threadIdx.x;
    for (int i = tid0; i < 2 * 512 * Hx; i += stride) d_h[i] = 0.f;
    if (tid0 == 0) d_bar = 0u;
}

// ---------------- weight reshapes ----------------------------------------------
__global__ void k_prep(const float* __restrict__ Wihf, const float* __restrict__ Whhf,
                       const float* __restrict__ bf,
                       const float* __restrict__ Wihb, const float* __restrict__ Whhb,
                       const float* __restrict__ bbv,
                       const float* __restrict__ c1w, const float* __restrict__ c2w) {
    int stride = gridDim.x * blockDim.x;
    int tid0 = blockIdx.x * blockDim.x + threadIdx.x;
    for (int idx = tid0; idx < Ex * G4; idx += stride) {
        int k = idx / G4, col = idx - k * G4;
        int j = col >> 2, g = col & 3;
        int src = (g * Hx + j) * Ex + k;   // Ex == Hx
        d_Wihf_t[idx] = Wihf[src];
        d_Wihb_t[idx] = Wihb[src];
        d_Whhf_t[idx] = Whhf[src];
        d_Whhb_t[idx] = Whhb[src];
    }
    for (int idx = tid0; idx < G4; idx += stride) {
        int j = idx >> 2, g = idx & 3;
        d_bif[idx] = bf[g * Hx + j];
        d_bib[idx] = bbv[g * Hx + j];
    }
    for (int idx = tid0; idx < KCONV * Cc; idx += stride) {
        int o = idx % Cc, r = idx / Cc;
        int kk = r / Cc, i = r - kk * Cc;
        size_t src = (size_t)o * KCONV + i * 3 + kk;
        d_cw1[idx] = c1w[src];
        d_cw2[idx] = c2w[src];
    }
}

// ---------------- embedding gather ---------------------------------------------
__global__ void k_embed(const int* __restrict__ cat, const float* __restrict__ emb) {
    int stride = gridDim.x * blockDim.x;
    for (int idx = blockIdx.x * blockDim.x + threadIdx.x; idx < Mx * (Ex / 4); idx += stride) {
        int m = idx / (Ex / 4), e4 = idx - m * (Ex / 4);
        *(float4*)&d_text[(size_t)m * Ex + e4 * 4] =
            *(const float4*)&emb[(size_t)cat[m] * Ex + e4 * 4];
    }
}

// ---------------- tf32 tensor-core GEMM, 128x128 block, BK=16 ------------------
// CFG 5: fused xg  A=d_text [65536x300], B=[Wihf_t | Wihb_t] N=2400, +bias
// CFG 4: conv1     A=d_ca   [512x1800],  B=cw1 [1800x600],   +bias, relu, *rowscale
#define LDSW 136
template <int CFG>
__global__ __launch_bounds__(256, 2)
void tgemm(const float* __restrict__ extbias) {
    constexpr bool FUSED = (CFG == 5);
    constexpr int  N     = FUSED ? 2400 : Cc;
    constexpr int  K     = FUSED ? Ex : KCONV;
    constexpr bool RELU  = (CFG == 4);
    constexpr bool RSCL  = (CFG == 4);
    constexpr int  BK    = 16;

    const float* A    = FUSED ? d_text : d_ca;
    const float* Bw   = d_cw1;           // only used when !FUSED
    const float* bias = extbias;         // only used when !FUSED
    float*       Cout = d_x2row;         // only used when !FUSED

    __shared__ float As[2][BK][LDSW];
    __shared__ float Bs[2][BK][LDSW];

    int tid = threadIdx.x;
    int lane = tid & 31, wid = tid >> 5;
    int wm = (wid & 1) * 64;
    int wn = (wid >> 1) * 32;
    int m0 = blockIdx.y * 128, n0 = blockIdx.x * 128;

    size_t abase[2]; int arow[2], akq[2];
    int bkr[2], bnq[2];
#pragma unroll
    for (int q = 0; q < 2; q++) {
        int pos = tid + 256 * q;
        arow[q] = pos >> 2;
        akq[q]  = (pos & 3) * 4;
        abase[q] = (size_t)(m0 + arow[q]) * K;
        bkr[q] = pos >> 5;
        bnq[q] = (pos & 31) * 4;
    }

    float4 ra[2], rb[2];
    auto load_tiles = [&](int k0) {
#pragma unroll
        for (int q = 0; q < 2; q++) {
            int k = k0 + akq[q];
            ra[q] = (k < K) ? *(const float4*)(A + abase[q] + k)
                            : make_float4(0.f, 0.f, 0.f, 0.f);
            int kb = k0 + bkr[q], n = n0 + bnq[q];
            rb[q] = make_float4(0.f, 0.f, 0.f, 0.f);
            if (kb < K) {
                if (FUSED) {
                    if (n < G4)        rb[q] = *(const float4*)(d_Wihf_t + (size_t)kb * G4 + n);
                    else if (n < 2400) rb[q] = *(const float4*)(d_Wihb_t + (size_t)kb * G4 + (n - G4));
                } else if (n < N) {
                    rb[q] = *(const float4*)(Bw + (size_t)kb * N + n);
                }
            }
        }
    };
    auto store_tiles = [&](int s) {
#pragma unroll
        for (int q = 0; q < 2; q++) {
            As[s][akq[q] + 0][arow[q]] = to_tf32(ra[q].x);
            As[s][akq[q] + 1][arow[q]] = to_tf32(ra[q].y);
            As[s][akq[q] + 2][arow[q]] = to_tf32(ra[q].z);
            As[s][akq[q] + 3][arow[q]] = to_tf32(ra[q].w);
            Bs[s][bkr[q]][bnq[q] + 0] = to_tf32(rb[q].x);
            Bs[s][bkr[q]][bnq[q] + 1] = to_tf32(rb[q].y);
            Bs[s][bkr[q]][bnq[q] + 2] = to_tf32(rb[q].z);
            Bs[s][bkr[q]][bnq[q] + 3] = to_tf32(rb[q].w);
        }
    };

    float acc[4][4][4];
#pragma unroll
    for (int i = 0; i < 4; i++)
#pragma unroll
        for (int j = 0; j < 4; j++)
#pragma unroll
            for (int q = 0; q < 4; q++) acc[i][j][q] = 0.f;

    int r = lane >> 2, c = lane & 3;

    auto compute = [&](int s) {
#pragma unroll
        for (int ks = 0; ks < 2; ks++) {
            int kb = ks * 8;
            uint32_t af[4][4], bf[4][2];
#pragma unroll
            for (int mt = 0; mt < 4; mt++) {
                int mb = wm + mt * 16 + r;
                af[mt][0] = __float_as_uint(As[s][kb + c][mb]);
                af[mt][1] = __float_as_uint(As[s][kb + c][mb + 8]);
                af[mt][2] = __float_as_uint(As[s][kb + c + 4][mb]);
                af[mt][3] = __float_as_uint(As[s][kb + c + 4][mb + 8]);
            }
#pragma unroll
            for (int nt = 0; nt < 4; nt++) {
                int nb = wn + nt * 8 + r;
                bf[nt][0] = __float_as_uint(Bs[s][kb + c][nb]);
                bf[nt][1] = __float_as_uint(Bs[s][kb + c + 4][nb]);
            }
#pragma unroll
            for (int mt = 0; mt < 4; mt++)
#pragma unroll
                for (int nt = 0; nt < 4; nt++) {
                    asm volatile(
                        "mma.sync.aligned.m16n8k8.row.col.f32.tf32.tf32.f32 "
                        "{%0,%1,%2,%3}, {%4,%5,%6,%7}, {%8,%9}, {%0,%1,%2,%3};"
                        : "+f"(acc[mt][nt][0]), "+f"(acc[mt][nt][1]),
                          "+f"(acc[mt][nt][2]), "+f"(acc[mt][nt][3])
                        : "r"(af[mt][0]), "r"(af[mt][1]), "r"(af[mt][2]), "r"(af[mt][3]),
                          "r"(bf[nt][0]), "r"(bf[nt][1]));
                }
        }
    };

    constexpr int NK = (K + BK - 1) / BK;
    load_tiles(0);
    store_tiles(0);
    __syncthreads();
    for (int it = 0; it < NK; it++) {
        if (it + 1 < NK) load_tiles((it + 1) * BK);
        compute(it & 1);
        if (it + 1 < NK) store_tiles((it + 1) & 1);
        __syncthreads();
    }

#pragma unroll
    for (int mt = 0; mt < 4; mt++) {
#pragma unroll
        for (int j2 = 0; j2 < 2; j2++) {
            int m = m0 + wm + mt * 16 + r + j2 * 8;
            float scl = RSCL ? d_rowscale[m] : 1.f;
#pragma unroll
            for (int nt = 0; nt < 4; nt++) {
                int n = n0 + wn + nt * 8 + c * 2;
#pragma unroll
                for (int jj = 0; jj < 2; jj++) {
                    int nn = n + jj;
                    float v = acc[mt][nt][j2 * 2 + jj];
                    if (FUSED) {
                        if (nn < G4)
                            d_xg_f[(size_t)m * G4 + nn] = v + d_bif[nn];
                        else if (nn < 2400)
                            d_xg_b[(size_t)m * G4 + (nn - G4)] = v + d_bib[nn - G4];
                    } else if (nn < N) {
                        v += bias[nn];
                        if (RELU) v = fmaxf(v, 0.f);
                        if (RSCL) v *= scl;
                        Cout[(size_t)m * N + nn] = v;
                    }
                }
            }
        }
    }
}

// ---------------- persistent LSTM: 256 steps, tf32 MMA, c-state in regs --------
// grid NBLK=152 = 19 col-tiles(64) x 8 row-tiles(64). Rows 0..255 fwd, 256..511 bwd.
#define WS_STRIDE 308
#define WS_FLOATS (64 * WS_STRIDE)      // 19712
#define AS_STRIDE 72
#define AS_FLOATS (2 * 16 * AS_STRIDE)  // 2304
#define LSTM_SMEM ((WS_FLOATS + AS_FLOATS) * 4)

__global__ __launch_bounds__(256, 2)
void lstm_persist() {
    extern __shared__ float sm[];
    float* Ws = sm;                 // Ws[col][k] : col*308 + k, k padded to 304
    float* Av = sm + WS_FLOATS;     // Av[buf][k][row] : buf*16*72 + k*72 + row

    int tid = threadIdx.x;
    int lane = tid & 31, wid = tid >> 5;
    int ct = blockIdx.x % 19, rt = blockIdx.x / 19;
    int col0 = ct * 64, row0 = rt * 64;
    bool bwd = (row0 >= 256);
    const float* Wt = bwd ? d_Whhb_t : d_Whhf_t;
    const float* xg = bwd ? d_xg_b : d_xg_f;

    // one-time: W tile -> smem (tf32), cols col0..col0+63, k 0..303 (pad 0)
    for (int i = tid; i < 64 * 304; i += 256) {
        int col = i / 304, k = i - col * 304;
        float v = 0.f;
        if (k < Hx && col0 + col < G4) v = Wt[(size_t)k * G4 + col0 + col];
        Ws[col * WS_STRIDE + k] = to_tf32(v);
    }
    __syncthreads();

    int r = lane >> 2, c = lane & 3;
    int wm = (wid & 3) * 16;        // 4 warps in m
    int wn = (wid >> 2) * 32;       // 2 warps in n
    bool evenc = ((c & 1) == 0);
    int row_g = row0 + wm + r + (evenc ? 0 : 8);   // my (row) for cell state
    int b = row_g & 255;
    int Lb = d_L[b];
    int jb = (col0 + wn) >> 2;
    int cpair = (c >> 1);

    // A-stage loader indexing: one float4 per thread per 16k chunk
    int lrow = tid >> 2;            // 0..63
    int lkq  = (tid & 3) * 4;       // 0,4,8,12

    float cst[4] = {0.f, 0.f, 0.f, 0.f};

    for (int t = 0; t < Sx; t++) {
        const float* hp = d_h + (size_t)(t & 1) * (512 * Hx);
        float*       hn = d_h + (size_t)((t + 1) & 1) * (512 * Hx);

        float acc[4][4];
#pragma unroll
        for (int nt = 0; nt < 4; nt++)
#pragma unroll
            for (int q = 0; q < 4; q++) acc[nt][q] = 0.f;

        float4 ra;
        auto lda = [&](int k0) {
            int k = k0 + lkq;
            ra = (k < Hx) ? *(const float4*)(hp + (size_t)(row0 + lrow) * Hx + k)
                          : make_float4(0.f, 0.f, 0.f, 0.f);
        };
        auto sta = [&](int s) {
            float* dst = Av + s * 16 * AS_STRIDE;
            dst[(lkq + 0) * AS_STRIDE + lrow] = to_tf32(ra.x);
            dst[(lkq + 1) * AS_STRIDE + lrow] = to_tf32(ra.y);
            dst[(lkq + 2) * AS_STRIDE + lrow] = to_tf32(ra.z);
            dst[(lkq + 3) * AS_STRIDE + lrow] = to_tf32(ra.w);
        };
        auto cmp = [&](int s, int kg0) {
            const float* av = Av + s * 16 * AS_STRIDE;
#pragma unroll
            for (int ks = 0; ks < 2; ks++) {
                int kb = ks * 8;
                uint32_t af[4], bf[4][2];
                int mb = wm + r;
                af[0] = __float_as_uint(av[(kb + c) * AS_STRIDE + mb]);
                af[1] = __float_as_uint(av[(kb + c) * AS_STRIDE + mb + 8]);
                af[2] = __float_as_uint(av[(kb + c + 4) * AS_STRIDE + mb]);
                af[3] = __float_as_uint(av[(kb + c + 4) * AS_STRIDE + mb + 8]);
                int kg = kg0 + kb;
#pragma unroll
                for (int nt = 0; nt < 4; nt++) {
                    int nb = wn + nt * 8 + r;
                    bf[nt][0] = __float_as_uint(Ws[nb * WS_STRIDE + kg + c]);
                    bf[nt][1] = __float_as_uint(Ws[nb * WS_STRIDE + kg + c + 4]);
                }
#pragma unroll
                for (int nt = 0; nt < 4; nt++) {
                    asm volatile(
                        "mma.sync.aligned.m16n8k8.row.col.f32.tf32.tf32.f32 "
                        "{%0,%1,%2,%3}, {%4,%5,%6,%7}, {%8,%9}, {%0,%1,%2,%3};"
                        : "+f"(acc[nt][0]), "+f"(acc[nt][1]),
                          "+f"(acc[nt][2]), "+f"(acc[nt][3])
                        : "r"(af[0]), "r"(af[1]), "r"(af[2]), "r"(af[3]),
                          "r"(bf[nt][0]), "r"(bf[nt][1]));
                }
            }
        };

        lda(0); sta(0);
        __syncthreads();
#pragma unroll 1
        for (int it = 0; it < 19; it++) {
            if (it + 1 < 19) lda((it + 1) * 16);
            cmp(it & 1, it * 16);
            if (it + 1 < 19) sta((it + 1) & 1);
            __syncthreads();
        }

        // epilogue: gate-pair exchange, cell update, h + text_out writes
        int tsrc = bwd ? ((t < Lb) ? (Lb - 1 - t) : t) : t;
        int pos  = bwd ? tsrc : t;
        const float* xgrow = xg + ((size_t)(b * Sx + tsrc)) * G4;
        float hvals[4]; int jidx[4];
#pragma unroll
        for (int nt = 0; nt < 4; nt++) {
            float d0 = acc[nt][0], d1 = acc[nt][1], d2 = acc[nt][2], d3 = acc[nt][3];
            float x0 = __shfl_xor_sync(0xFFFFFFFFu, evenc ? d2 : d0, 1);
            float x1 = __shfl_xor_sync(0xFFFFFFFFu, evenc ? d3 : d1, 1);
            float gi = evenc ? d0 : x0;
            float gf = evenc ? d1 : x1;
            float gg = evenc ? x0 : d2;
            float go = evenc ? x1 : d3;
            int j = jb + nt * 2 + cpair;
            jidx[nt] = j;
            if (j < Hx) {
                float4 xv = *(const float4*)(xgrow + j * 4);
                gi += xv.x; gf += xv.y; gg += xv.z; go += xv.w;
                float si = 1.f / (1.f + expf(-gi));
                float sf = 1.f / (1.f + expf(-gf));
                float so = 1.f / (1.f + expf(-go));
                float cn = sf * cst[nt] + si * tanhf(gg);
                cst[nt] = cn;
                hvals[nt] = so * tanhf(cn);
            } else hvals[nt] = 0.f;
        }
        size_t hbase = (size_t)row_g * Hx;
        size_t tbase = ((size_t)(b * Sx + pos)) * Cc + (bwd ? Hx : 0);
        float mask = (t < Lb) ? 1.f : 0.f;
#pragma unroll
        for (int nt = 0; nt < 4; nt++) {
            if (jidx[nt] < Hx) {
                hn[hbase + jidx[nt]] = hvals[nt];
                d_to[tbase + jidx[nt]] = hvals[nt] * mask;
            }
        }

        // grid barrier
        __syncthreads();
        if (tid == 0) {
            __threadfence();
            atomicAdd(&d_bar, 1u);
            unsigned target = (unsigned)NBLK * (unsigned)(t + 1);
            while (*(volatile unsigned*)&d_bar < target) __nanosleep(64);
            __threadfence();
        }
        __syncthreads();
    }
}

// ---------------- gather conv1 input windows (2 rows per batch) -----------------
__global__ void k_gatherca() {
    int rr = blockIdx.x;
    int b = rr >> 1, side = rr & 1;
    int le = d_left[b];
    int rt = le + d_asp[b] - 1;
    int p = side ? (rt + 1) : (le - 1);
    bool valid = (p >= 0 && p < Sx);
    if (threadIdx.x == 0)
        d_rowscale[rr] = valid ? d_pw[b * Sx + p] : 0.f;
    for (int k = threadIdx.x; k < KCONV; k += blockDim.x) {
        int dk = k / Cc, i = k - dk * Cc;
        int prow = p - 1 + dk;
        float val = 0.f;
        if (valid && prow >= 0 && prow < Sx)
            val = d_to[((size_t)(b * Sx + prow)) * Cc + i] * d_pw[b * Sx + prow];
        d_ca[(size_t)rr * KCONV + k] = val;
    }
}

// ---------------- conv2 on the two nonzero rows + v ----------------------------
__global__ void k_vrow(const float* __restrict__ c2bias) {
    __shared__ float s0[Cc], s1[Cc];
    int b = blockIdx.x, tid = threadIdx.x;
    int a = d_asp[b];
    for (int i = tid; i < Cc; i += blockDim.x) {
        s0[i] = d_x2row[(size_t)(b * 2 + 0) * Cc + i];
        s1[i] = d_x2row[(size_t)(b * 2 + 1) * Cc + i];
    }
    __syncthreads();
    float acc0[3] = {0.f, 0.f, 0.f}, acc1[3] = {0.f, 0.f, 0.f};
    for (int i = 0; i < Cc; i++) {
        float a0 = s0[i], a1 = s1[i];
        const float* w0 = d_cw2 + (size_t)i * Cc;
        const float* w2 = d_cw2 + (size_t)(1200 + i) * Cc;
#pragma unroll
        for (int q = 0; q < 3; q++) {
            int o = tid + q * 256;
            if (o < Cc) {
                acc0[q] = fmaf(w0[o], a0, acc0[q]);
                acc1[q] = fmaf(w2[o], a1, acc1[q]);
            }
        }
    }
#pragma unroll
    for (int q = 0; q < 3; q++) {
        int o = tid + q * 256;
        if (o < Cc) {
            float bb = c2bias[o];
            float v;
            if (a == 1) {
                v = fmaxf(acc0[q] + acc1[q] + bb, 0.f);
            } else {
                v = fmaxf(acc0[q] + bb, 0.f) + fmaxf(acc1[q] + bb, 0.f)
                  + (float)(a - 2) * fmaxf(bb, 0.f);
            }
            d_v[b * Cc + o] = v;
        }
    }
}

// ---------------- logits -------------------------------------------------------
__global__ void k_logits() {
    int b = blockIdx.x;
    int w = threadIdx.x >> 5, lane = threadIdx.x & 31;
    int t = blockIdx.y * 8 + w;
    const float* vb = d_v + (size_t)b * Cc;
    const float* to = d_to + ((size_t)(b * Sx + t)) * Cc;
    float s = 0.f;
    for (int c = lane; c < Cc; c += 32) s = fmaf(vb[c], to[c], s);
#pragma unroll
    for (int o = 16; o; o >>= 1) s += __shfl_xor_sync(0xFFFFFFFFu, s, o);
    if (lane == 0) d_logits[b * Sx + t] = s;
}

// ---------------- softmax + feat + fc ------------------------------------------
__global__ void k_final(const float* __restrict__ fcw, const float* __restrict__ fcb,
                        float* __restrict__ out) {
    __shared__ float sred[256];
    __shared__ float salpha[256];
    __shared__ float feat[Cc];
    int b = blockIdx.x, t = threadIdx.x;
    float lg = d_logits[b * Sx + t];
    sred[t] = lg;
    __syncthreads();
    for (int o = 128; o; o >>= 1) { if (t < o) sred[t] = fmaxf(sred[t], sred[t + o]); __syncthreads(); }
    float mx = sred[0];
    __syncthreads();
    float e = expf(lg - mx);
    salpha[t] = e;
    sred[t] = e;
    __syncthreads();
    for (int o = 128; o; o >>= 1) { if (t < o) sred[t] += sred[t + o]; __syncthreads(); }
    float Z = sred[0];
    __syncthreads();
    for (int c = t; c < Cc; c += 256) {
        float f = 0.f;
        for (int tt = 0; tt < Sx; tt++)
            f = fmaf(salpha[tt], d_to[((size_t)(b * Sx + tt)) * Cc + c], f);
        feat[c] = f / Z;
    }
    __syncthreads();
    for (int p = 0; p < 3; p++) {
        float part = 0.f;
        for (int c = t; c < Cc; c += 256) part = fmaf(feat[c], fcw[p * Cc + c], part);
        sred[t] = part;
        __syncthreads();
        for (int o = 128; o; o >>= 1) { if (t < o) sred[t] += sred[t + o]; __syncthreads(); }
        if (t == 0) out[b * 3 + p] = sred[0] + fcb[p];
        __syncthreads();
    }
}

// ---------------- launch -------------------------------------------------------
extern "C" void kernel_launch(void* const* d_in, const int* in_sizes, int n_in,
                              void* d_out, int out_size) {
    (void)in_sizes; (void)n_in; (void)out_size;
    const int*   cat   = (const int*)d_in[0];
    const int*   aspi  = (const int*)d_in[1];
    const int*   lefti = (const int*)d_in[2];
    const float* emb   = (const float*)d_in[3];
    const float* Wihf  = (const float*)d_in[4];
    const float* Whhf  = (const float*)d_in[5];
    const float* bf    = (const float*)d_in[6];
    const float* Wihb  = (const float*)d_in[7];
    const float* Whhb  = (const float*)d_in[8];
    const float* bbv   = (const float*)d_in[9];
    const float* c1w   = (const float*)d_in[10];
    const float* c1b   = (const float*)d_in[11];
    const float* c2w   = (const float*)d_in[12];
    const float* c2b   = (const float*)d_in[13];
    const float* fcw   = (const float*)d_in[14];
    const float* fcb   = (const float*)d_in[15];
    float* out = (float*)d_out;

    cudaFuncSetAttribute(lstm_persist, cudaFuncAttributeMaxDynamicSharedMemorySize,
                         LSTM_SMEM);

    k_meta<<<Bx, 256>>>(cat, aspi, lefti);
    k_zero<<<512, 256>>>();
    k_prep<<<2048, 256>>>(Wihf, Whhf, bf, Wihb, Whhb, bbv, c1w, c2w);
    k_embed<<<4096, 256>>>(cat, emb);

    dim3 g1(19, 512);   // N=2400 fused, M=65536
    tgemm<5><<<g1, 256>>>(nullptr);

    lstm_persist<<<NBLK, 256, LSTM_SMEM>>>();

    k_gatherca<<<512, 256>>>();
    dim3 g2(5, 4);      // N=600, M=512
    tgemm<4><<<g2, 256>>>(c1b);
    k_vrow<<<Bx, 256>>>(c2b);

    dim3 g3(Bx, 32);
    k_logits<<<g3, 256>>>();
    k_final<<<Bx, 256>>>(fcw, fcb, out);
}